// round 11
// baseline (speedup 1.0000x reference)
#include <cuda_runtime.h>
#include <cstdint>
#include <math.h>

#define BN 2048
#define DN 3072
#define CN 10
#define MN 9

#define ALPHA  0.999999f             // 1 - C*NUM_STAB
#define NST    1e-7f
#define RS10   0.31622776601683794f  // 1/sqrt(10)

typedef unsigned long long u64;
typedef unsigned int u32;

// packed fp32x2 FMA: acc.{lo,hi} += a.{lo,hi} * b.{lo,hi}
#define FMA_X2(acc, a, b) \
    asm("fma.rn.f32x2 %0, %1, %2, %0;" : "+l"(acc) : "l"(a), "l"(b))
#define UNPACK_X2(lo, hi, v) \
    asm("mov.b64 {%0, %1}, %2;" : "=f"(lo), "=f"(hi) : "l"(v))

#define MBAR_INIT(a, n) \
    asm volatile("mbarrier.init.shared.b64 [%0], %1;" :: "r"(a), "r"(n) : "memory")
#define MBAR_EXPECT_TX(a, n) \
    asm volatile("mbarrier.arrive.expect_tx.shared.b64 _, [%0], %1;" :: "r"(a), "r"(n) : "memory")
#define CP_BULK_CTA(dst, src, bytes, mbar) \
    asm volatile("cp.async.bulk.shared::cta.global.mbarrier::complete_tx::bytes [%0], [%1], %2, [%3];" \
        :: "r"(dst), "l"(src), "r"(bytes), "r"(mbar) : "memory")
// Fire-and-forget DRAM->L2 prefetch; consumes no SM-side miss slots.
#define CP_BULK_PREFETCH_L2(src, bytes) \
    asm volatile("cp.async.bulk.prefetch.L2.global [%0], %1;" :: "l"(src), "r"(bytes) : "memory")

__device__ __forceinline__ void mbar_wait(u32 mbar, u32 parity) {
    u32 done;
    asm volatile(
        "{\n\t.reg .pred p;\n\t"
        "mbarrier.try_wait.parity.acquire.cta.shared::cta.b64 p, [%1], %2;\n\t"
        "selp.b32 %0, 1, 0, p;\n\t}"
        : "=r"(done) : "r"(mbar), "r"(parity) : "memory");
    if (!done) {
        asm volatile(
            "{\n\t.reg .pred P1;\n\t"
            "WL%=:\n\t"
            "mbarrier.try_wait.parity.acquire.cta.shared::cta.b64 P1, [%0], %1, 0x989680;\n\t"
            "@P1 bra.uni WD%=;\n\t"
            "bra.uni WL%=;\n\t"
            "WD%=:\n\t}"
            :: "r"(mbar), "r"(parity) : "memory");
    }
}

// Scratch (no allocations allowed)
__device__ __align__(16) float g_Wt[CN * DN];    // W transposed [C][D]
__device__ float g_Wg[CN * CN];                  // W^T W

// ---------------------------------------------------------------------------
// Prep: blocks 0..11 transpose W -> Wt; blocks 12..21 compute Wg rows.
// ---------------------------------------------------------------------------
__global__ void __launch_bounds__(256) prep_kernel(const float* __restrict__ W) {
    int bid = blockIdx.x;
    int tid = threadIdx.x;
    if (bid < 12) {
        int d = bid * 256 + tid;
        float w[CN];
        #pragma unroll
        for (int c = 0; c < CN; c++) w[c] = __ldg(&W[d * CN + c]);
        #pragma unroll
        for (int c = 0; c < CN; c++) g_Wt[c * DN + d] = w[c];
    } else {
        int i = bid - 12;
        float acc[CN];
        #pragma unroll
        for (int j = 0; j < CN; j++) acc[j] = 0.f;
        for (int d = tid; d < DN; d += 256) {
            float w[CN];
            #pragma unroll
            for (int j = 0; j < CN; j++) w[j] = __ldg(&W[d * CN + j]);
            float wi = w[i];
            #pragma unroll
            for (int j = 0; j < CN; j++) acc[j] = fmaf(wi, w[j], acc[j]);
        }
        #pragma unroll
        for (int j = 0; j < CN; j++) {
            #pragma unroll
            for (int off = 16; off > 0; off >>= 1)
                acc[j] += __shfl_xor_sync(0xffffffffu, acc[j], off);
        }
        __shared__ float smem[8][CN];
        int w_ = tid >> 5, l = tid & 31;
        if (l == 0) {
            #pragma unroll
            for (int j = 0; j < CN; j++) smem[w_][j] = acc[j];
        }
        __syncthreads();
        if (tid < CN) {
            float s = 0.f;
            #pragma unroll
            for (int k = 0; k < 8; k++) s += smem[k][tid];
            g_Wg[i * CN + tid] = s;
        }
    }
}

// ---------------------------------------------------------------------------
// Hybrid main kernel + L2 prefetch: 128 blocks x 512 threads, 16 samples.
// Step 0: each warp (lane 0) issues cp.async.bulk.prefetch.L2 for one
//         sample's 12KB -> entire block working set headed to L2 at t~0.
// Samples 0-7: TMA bulk -> smem (8 x 12KB, one mbarrier), warps 0-7.
// Samples 8-15: direct ld.global.cs, warps 8-15 (LSU engine).
// Both halves: FFMA2, W via __ldg. Fused epilogue.
// ---------------------------------------------------------------------------
extern __shared__ __align__(16) float4 xsm[];    // [8 samples][768 float4] = 96KB

__global__ void __launch_bounds__(512, 1) main_kernel(const float* __restrict__ data,
                                                      const float* __restrict__ bias,
                                                      float* __restrict__ out) {
    __shared__ __align__(8) u64 mbar_s;
    __shared__ float smred[8][16][CN];           // [kidx][sample][class]

    const int tid   = threadIdx.x;
    const int wid   = tid >> 5;
    const int lane  = tid & 31;
    const int kidx  = wid & 7;                   // K-eighth (96 float4)
    const int octet = wid >> 3;                  // 0 = TMA half, 1 = LDG half
    const int pgrp  = lane >> 3;                 // sample pair within half
    const int klane = lane & 7;

    const int ls = pgrp * 2;                     // local sample within half
    const int s0 = blockIdx.x * 16;              // block's first sample

    const char* blk = reinterpret_cast<const char*>(data) + (size_t)s0 * (DN * 4);

    // ---- step 0: L2 prefetch of the whole block (16 x 12KB) ---------------
    if (lane == 0)
        CP_BULK_PREFETCH_L2(blk + (size_t)wid * 12288u, 12288u);

    const u32 mbar = (u32)__cvta_generic_to_shared(&mbar_s);
    const u32 xsa  = (u32)__cvta_generic_to_shared(xsm);

    if (tid == 0) MBAR_INIT(mbar, 1);
    __syncthreads();

    if (tid == 0) {
        MBAR_EXPECT_TX(mbar, 98304u);
        #pragma unroll
        for (int j = 0; j < 8; j++)
            CP_BULK_CTA(xsa + j * 12288u, blk + (size_t)j * 12288u, 12288u, mbar);
    }

    const ulonglong2* __restrict__ wt = reinterpret_cast<const ulonglong2*>(g_Wt);
    const int kw = kidx * 96 + klane;            // W float4 base index

    u64 a0[CN], a1[CN];
    #pragma unroll
    for (int c = 0; c < CN; c++) { a0[c] = 0ull; a1[c] = 0ull; }

    if (octet == 0) {
        // ---- TMA half: wait for smem fill, compute from SMEM --------------
        mbar_wait(mbar, 0);
        const ulonglong2* __restrict__ xs = reinterpret_cast<const ulonglong2*>(xsm);
        const ulonglong2* __restrict__ x0 = xs + (size_t)ls * 768 + kw;
        #pragma unroll
        for (int i = 0; i < 12; i++) {
            ulonglong2 xv0 = x0[i * 8];
            ulonglong2 xv1 = x0[768 + i * 8];
            #pragma unroll
            for (int c = 0; c < CN; c++) {
                ulonglong2 wv = __ldg(&wt[c * 768 + kw + i * 8]);
                FMA_X2(a0[c], xv0.x, wv.x);
                FMA_X2(a0[c], xv0.y, wv.y);
                FMA_X2(a1[c], xv1.x, wv.x);
                FMA_X2(a1[c], xv1.y, wv.y);
            }
        }
    } else {
        // ---- LDG half: stream directly from gmem (LSU engine) -------------
        const char* xb0 = blk + (size_t)(8 + ls) * (DN * 4);
        const char* xb1 = xb0 + DN * 4;
        #pragma unroll 4
        for (int i = 0; i < 12; i++) {
            int k4 = kw + i * 8;
            u64 x0lo, x0hi, x1lo, x1hi;
            asm("ld.global.cs.v2.u64 {%0, %1}, [%2];"
                : "=l"(x0lo), "=l"(x0hi) : "l"(xb0 + (size_t)k4 * 16));
            asm("ld.global.cs.v2.u64 {%0, %1}, [%2];"
                : "=l"(x1lo), "=l"(x1hi) : "l"(xb1 + (size_t)k4 * 16));
            #pragma unroll
            for (int c = 0; c < CN; c++) {
                ulonglong2 wv = __ldg(&wt[c * 768 + kw + i * 8]);
                FMA_X2(a0[c], x0lo, wv.x);
                FMA_X2(a0[c], x0hi, wv.y);
                FMA_X2(a1[c], x1lo, wv.x);
                FMA_X2(a1[c], x1hi, wv.y);
            }
        }
    }

    // unpack, reduce across 8 klanes (xor 1,2,4 stay within pgrp)
    float f0[CN], f1[CN];
    #pragma unroll
    for (int c = 0; c < CN; c++) {
        float lo, hi;
        UNPACK_X2(lo, hi, a0[c]); f0[c] = lo + hi;
        UNPACK_X2(lo, hi, a1[c]); f1[c] = lo + hi;
    }
    #pragma unroll
    for (int c = 0; c < CN; c++) {
        #pragma unroll
        for (int off = 4; off > 0; off >>= 1) {
            f0[c] += __shfl_xor_sync(0xffffffffu, f0[c], off);
            f1[c] += __shfl_xor_sync(0xffffffffu, f1[c], off);
        }
    }
    if (klane == 0) {
        int srow = octet * 8 + ls;
        #pragma unroll
        for (int c = 0; c < CN; c++) {
            smred[kidx][srow][c]     = f0[c];
            smred[kidx][srow + 1][c] = f1[c];
        }
    }
    __syncthreads();

    // ---- fused epilogue: 16 threads, one per sample ------------------------
    if (tid < 16) {
        float l[CN];
        #pragma unroll
        for (int c = 0; c < CN; c++) {
            float a = __ldg(&bias[c]);
            #pragma unroll
            for (int k = 0; k < 8; k++) a += smred[k][tid][c];
            l[c] = a;
        }

        float mx = l[0];
        #pragma unroll
        for (int c = 1; c < CN; c++) mx = fmaxf(mx, l[c]);

        float e[CN], Z = 0.f;
        #pragma unroll
        for (int c = 0; c < CN; c++) { e[c] = expf(l[c] - mx); Z += e[c]; }
        float invZ = 1.f / Z;

        float s[CN], r[CN], sumr = 0.f;
        #pragma unroll
        for (int c = 0; c < CN; c++) {
            s[c] = e[c] * invZ;
            float p = fmaf(s[c], ALPHA, NST);
            r[c] = sqrtf(p);
            sumr += r[c];
        }
        float u = 1.f - r[MN];
        float delta = 2.f * acosf(fminf(sumr * RS10, 1.f));

        float wg[CN * CN];
        #pragma unroll
        for (int v = 0; v < CN * CN; v++) wg[v] = __ldg(&g_Wg[v]);

        float q[CN];
        #pragma unroll
        for (int j = 0; j < CN; j++) {
            float a = 0.f;
            #pragma unroll
            for (int k = 0; k < CN; k++) a = fmaf(s[k], wg[k * CN + j], a);
            q[j] = a;
        }
        float qs = 0.f;
        #pragma unroll
        for (int j = 0; j < CN; j++) qs = fmaf(q[j], s[j], qs);

        float inv_u = 1.f / u;
        float c2com = ALPHA * s[MN] * inv_u * inv_u / r[MN];
        float c1[MN], c2[MN], t[MN];
        #pragma unroll
        for (int m = 0; m < MN; m++) {
            c1[m] = ALPHA * s[m] * inv_u / r[m];
            c2[m] = c2com * r[m];
            t[m]  = c1[m] + c2[m];
        }

        float col[MN];
        #pragma unroll
        for (int n = 0; n < MN; n++) col[n] = 0.f;
        float norminf = 0.f;

        #pragma unroll
        for (int m = 0; m < MN; m++) {
            float Mrow[CN];
            #pragma unroll
            for (int j = 0; j < CN; j++)
                Mrow[j] = c1[m] * wg[m * CN + j] + c2[m] * wg[MN * CN + j] - t[m] * q[j];
            float wm = c1[m] * q[m] + c2[m] * q[MN] - t[m] * qs;
            float rowsum = 0.f;
            #pragma unroll
            for (int n = 0; n < MN; n++) {
                float g2 = c1[n] * Mrow[n] + c2[n] * Mrow[MN] - t[n] * wm;
                float ag = fabsf(g2);
                rowsum += ag;
                col[n] += ag;
            }
            norminf = fmaxf(norminf, rowsum);
        }
        float norm1 = 0.f;
        #pragma unroll
        for (int n = 0; n < MN; n++) norm1 = fmaxf(norm1, col[n]);

        float u2 = u * u;
        float jn = u2 * sqrtf(norm1 * norminf);
        out[s0 + tid] = delta / (0.1f * jn);
    }
}

// ---------------------------------------------------------------------------
extern "C" void kernel_launch(void* const* d_in, const int* in_sizes, int n_in,
                              void* d_out, int out_size) {
    const float* data = (const float*)d_in[0];   // [2048,3,32,32]
    const float* W    = (const float*)d_in[1];   // [3072,10]
    const float* bias = (const float*)d_in[2];   // [10]
    float* out = (float*)d_out;                  // [2048,1]

    static int configured = 0;
    if (!configured) {
        cudaFuncSetAttribute(main_kernel,
                             cudaFuncAttributeMaxDynamicSharedMemorySize,
                             98304 + 10240);
        configured = 1;
    }

    prep_kernel<<<22, 256>>>(W);
    main_kernel<<<128, 512, 98304>>>(data, bias, out);
}

// round 12
// speedup vs baseline: 1.0507x; 1.0507x over previous
#include <cuda_runtime.h>
#include <cstdint>
#include <math.h>

#define BN 2048
#define DN 3072
#define CN 10
#define MN 9

#define ALPHA  0.999999f             // 1 - C*NUM_STAB
#define NST    1e-7f
#define RS10   0.31622776601683794f  // 1/sqrt(10)

typedef unsigned long long u64;
typedef unsigned int u32;

// packed fp32x2 FMA: acc.{lo,hi} += a.{lo,hi} * b.{lo,hi}
#define FMA_X2(acc, a, b) \
    asm("fma.rn.f32x2 %0, %1, %2, %0;" : "+l"(acc) : "l"(a), "l"(b))
#define UNPACK_X2(lo, hi, v) \
    asm("mov.b64 {%0, %1}, %2;" : "=f"(lo), "=f"(hi) : "l"(v))

#define MBAR_INIT(a, n) \
    asm volatile("mbarrier.init.shared.b64 [%0], %1;" :: "r"(a), "r"(n) : "memory")
#define MBAR_EXPECT_TX(a, n) \
    asm volatile("mbarrier.arrive.expect_tx.shared.b64 _, [%0], %1;" :: "r"(a), "r"(n) : "memory")
#define CP_BULK_CTA(dst, src, bytes, mbar) \
    asm volatile("cp.async.bulk.shared::cta.global.mbarrier::complete_tx::bytes [%0], [%1], %2, [%3];" \
        :: "r"(dst), "l"(src), "r"(bytes), "r"(mbar) : "memory")

__device__ __forceinline__ void mbar_wait(u32 mbar, u32 parity) {
    u32 done;
    asm volatile(
        "{\n\t.reg .pred p;\n\t"
        "mbarrier.try_wait.parity.acquire.cta.shared::cta.b64 p, [%1], %2;\n\t"
        "selp.b32 %0, 1, 0, p;\n\t}"
        : "=r"(done) : "r"(mbar), "r"(parity) : "memory");
    if (!done) {
        asm volatile(
            "{\n\t.reg .pred P1;\n\t"
            "WL%=:\n\t"
            "mbarrier.try_wait.parity.acquire.cta.shared::cta.b64 P1, [%0], %1, 0x989680;\n\t"
            "@P1 bra.uni WD%=;\n\t"
            "bra.uni WL%=;\n\t"
            "WD%=:\n\t}"
            :: "r"(mbar), "r"(parity) : "memory");
    }
}

// Scratch (no allocations allowed)
__device__ __align__(16) float g_Wt[CN * DN];    // W transposed [C][D]
__device__ float g_Wg[CN * CN];                  // W^T W

// ---------------------------------------------------------------------------
// Prep: blocks 0..11 transpose W -> Wt; blocks 12..21 compute Wg rows.
// ---------------------------------------------------------------------------
__global__ void __launch_bounds__(256) prep_kernel(const float* __restrict__ W) {
    int bid = blockIdx.x;
    int tid = threadIdx.x;
    if (bid < 12) {
        int d = bid * 256 + tid;
        float w[CN];
        #pragma unroll
        for (int c = 0; c < CN; c++) w[c] = __ldg(&W[d * CN + c]);
        #pragma unroll
        for (int c = 0; c < CN; c++) g_Wt[c * DN + d] = w[c];
    } else {
        int i = bid - 12;
        float acc[CN];
        #pragma unroll
        for (int j = 0; j < CN; j++) acc[j] = 0.f;
        for (int d = tid; d < DN; d += 256) {
            float w[CN];
            #pragma unroll
            for (int j = 0; j < CN; j++) w[j] = __ldg(&W[d * CN + j]);
            float wi = w[i];
            #pragma unroll
            for (int j = 0; j < CN; j++) acc[j] = fmaf(wi, w[j], acc[j]);
        }
        #pragma unroll
        for (int j = 0; j < CN; j++) {
            #pragma unroll
            for (int off = 16; off > 0; off >>= 1)
                acc[j] += __shfl_xor_sync(0xffffffffu, acc[j], off);
        }
        __shared__ float smem[8][CN];
        int w_ = tid >> 5, l = tid & 31;
        if (l == 0) {
            #pragma unroll
            for (int j = 0; j < CN; j++) smem[w_][j] = acc[j];
        }
        __syncthreads();
        if (tid < CN) {
            float s = 0.f;
            #pragma unroll
            for (int k = 0; k < 8; k++) s += smem[k][tid];
            g_Wg[i * CN + tid] = s;
        }
    }
}

// ---------------------------------------------------------------------------
// Hybrid main kernel, full-chip grid: 148 blocks x 512 threads.
// Blocks 0-123: 14 samples; blocks 124-147: 13 samples (124*14+24*13=2048).
// Samples 0-6: TMA bulk -> smem (7 x 12KB, one mbarrier), warps 0-7.
// Samples 7..cnt-1: direct ld.global.cs, warps 8-15 (clamped for tail).
// smred rows: TMA -> 0..6 (+unused 7), LDG -> 8..8+nL-1 (rest unused).
// Both halves: FFMA2, W via __ldg. Fused epilogue over cnt samples.
// ---------------------------------------------------------------------------
extern __shared__ __align__(16) float4 xsm[];    // [7 samples][768 float4] = 84KB (+slack)

__global__ void __launch_bounds__(512, 1) main_kernel(const float* __restrict__ data,
                                                      const float* __restrict__ bias,
                                                      float* __restrict__ out) {
    __shared__ __align__(8) u64 mbar_s;
    __shared__ float smred[8][16][CN];           // [kidx][row][class]

    const int tid   = threadIdx.x;
    const int wid   = tid >> 5;
    const int lane  = tid & 31;
    const int kidx  = wid & 7;                   // K-eighth (96 float4)
    const int octet = wid >> 3;                  // 0 = TMA half, 1 = LDG half
    const int pgrp  = lane >> 3;                 // sample pair within half
    const int klane = lane & 7;

    const int bid  = blockIdx.x;
    const bool big = (bid < 124);
    const int cnt  = big ? 14 : 13;              // samples this block
    const int s0   = big ? bid * 14 : 1736 + (bid - 124) * 13;
    const int nL   = cnt - 7;                    // LDG-half sample count (7 or 6)

    const int ls = pgrp * 2;                     // local sample pair base within half
    const char* blk = reinterpret_cast<const char*>(data) + (size_t)s0 * (DN * 4);

    const u32 mbar = (u32)__cvta_generic_to_shared(&mbar_s);
    const u32 xsa  = (u32)__cvta_generic_to_shared(xsm);

    if (tid == 0) MBAR_INIT(mbar, 1);
    __syncthreads();

    if (tid == 0) {
        MBAR_EXPECT_TX(mbar, 86016u);            // 7 x 12KB
        #pragma unroll
        for (int j = 0; j < 7; j++)
            CP_BULK_CTA(xsa + j * 12288u, blk + (size_t)j * 12288u, 12288u, mbar);
    }

    const ulonglong2* __restrict__ wt = reinterpret_cast<const ulonglong2*>(g_Wt);
    const int kw = kidx * 96 + klane;            // W float4 base index

    u64 a0[CN], a1[CN];
    #pragma unroll
    for (int c = 0; c < CN; c++) { a0[c] = 0ull; a1[c] = 0ull; }

    if (octet == 0) {
        // ---- TMA half: samples 0-6 (pgrp3's 2nd slot unused garbage) -------
        mbar_wait(mbar, 0);
        const ulonglong2* __restrict__ xs = reinterpret_cast<const ulonglong2*>(xsm);
        // clamp pgrp3's second-sample row to row 6 (valid smem, result unused)
        const int r0 = ls;                        // 0,2,4,6
        const int r1 = (ls + 1 < 7) ? ls + 1 : 6;
        const ulonglong2* x0 = xs + (size_t)r0 * 768 + kw;
        const ulonglong2* x1 = xs + (size_t)r1 * 768 + kw;
        #pragma unroll
        for (int i = 0; i < 12; i++) {
            ulonglong2 xv0 = x0[i * 8];
            ulonglong2 xv1 = x1[i * 8];
            #pragma unroll
            for (int c = 0; c < CN; c++) {
                ulonglong2 wv = __ldg(&wt[c * 768 + kw + i * 8]);
                FMA_X2(a0[c], xv0.x, wv.x);
                FMA_X2(a0[c], xv0.y, wv.y);
                FMA_X2(a1[c], xv1.x, wv.x);
                FMA_X2(a1[c], xv1.y, wv.y);
            }
        }
    } else {
        // ---- LDG half: samples 7..cnt-1, clamped addresses for tail -------
        const int g0 = (ls     < nL) ? 7 + ls     : 0;   // clamp to sample 0
        const int g1 = (ls + 1 < nL) ? 8 + ls     : 0;
        const char* xb0 = blk + (size_t)g0 * (DN * 4);
        const char* xb1 = blk + (size_t)g1 * (DN * 4);
        #pragma unroll 4
        for (int i = 0; i < 12; i++) {
            int k4 = kw + i * 8;
            u64 x0lo, x0hi, x1lo, x1hi;
            asm("ld.global.cs.v2.u64 {%0, %1}, [%2];"
                : "=l"(x0lo), "=l"(x0hi) : "l"(xb0 + (size_t)k4 * 16));
            asm("ld.global.cs.v2.u64 {%0, %1}, [%2];"
                : "=l"(x1lo), "=l"(x1hi) : "l"(xb1 + (size_t)k4 * 16));
            #pragma unroll
            for (int c = 0; c < CN; c++) {
                ulonglong2 wv = __ldg(&wt[c * 768 + kw + i * 8]);
                FMA_X2(a0[c], x0lo, wv.x);
                FMA_X2(a0[c], x0hi, wv.y);
                FMA_X2(a1[c], x1lo, wv.x);
                FMA_X2(a1[c], x1hi, wv.y);
            }
        }
    }

    // unpack, reduce across 8 klanes (xor 1,2,4 stay within pgrp)
    float f0[CN], f1[CN];
    #pragma unroll
    for (int c = 0; c < CN; c++) {
        float lo, hi;
        UNPACK_X2(lo, hi, a0[c]); f0[c] = lo + hi;
        UNPACK_X2(lo, hi, a1[c]); f1[c] = lo + hi;
    }
    #pragma unroll
    for (int c = 0; c < CN; c++) {
        #pragma unroll
        for (int off = 4; off > 0; off >>= 1) {
            f0[c] += __shfl_xor_sync(0xffffffffu, f0[c], off);
            f1[c] += __shfl_xor_sync(0xffffffffu, f1[c], off);
        }
    }
    if (klane == 0) {
        int srow = octet * 8 + ls;               // TMA: 0..6(7), LDG: 8..15
        #pragma unroll
        for (int c = 0; c < CN; c++) {
            smred[kidx][srow][c]     = f0[c];
            smred[kidx][srow + 1][c] = f1[c];
        }
    }
    __syncthreads();

    // ---- fused epilogue: cnt threads, one per sample -----------------------
    if (tid < cnt) {
        const int row = (tid < 7) ? tid : tid + 1;   // skip unused row 7

        float l[CN];
        #pragma unroll
        for (int c = 0; c < CN; c++) {
            float a = __ldg(&bias[c]);
            #pragma unroll
            for (int k = 0; k < 8; k++) a += smred[k][row][c];
            l[c] = a;
        }

        float mx = l[0];
        #pragma unroll
        for (int c = 1; c < CN; c++) mx = fmaxf(mx, l[c]);

        float e[CN], Z = 0.f;
        #pragma unroll
        for (int c = 0; c < CN; c++) { e[c] = expf(l[c] - mx); Z += e[c]; }
        float invZ = 1.f / Z;

        float s[CN], r[CN], sumr = 0.f;
        #pragma unroll
        for (int c = 0; c < CN; c++) {
            s[c] = e[c] * invZ;
            float p = fmaf(s[c], ALPHA, NST);
            r[c] = sqrtf(p);
            sumr += r[c];
        }
        float u = 1.f - r[MN];
        float delta = 2.f * acosf(fminf(sumr * RS10, 1.f));

        float wg[CN * CN];
        #pragma unroll
        for (int v = 0; v < CN * CN; v++) wg[v] = __ldg(&g_Wg[v]);

        float q[CN];
        #pragma unroll
        for (int j = 0; j < CN; j++) {
            float a = 0.f;
            #pragma unroll
            for (int k = 0; k < CN; k++) a = fmaf(s[k], wg[k * CN + j], a);
            q[j] = a;
        }
        float qs = 0.f;
        #pragma unroll
        for (int j = 0; j < CN; j++) qs = fmaf(q[j], s[j], qs);

        float inv_u = 1.f / u;
        float c2com = ALPHA * s[MN] * inv_u * inv_u / r[MN];
        float c1[MN], c2[MN], t[MN];
        #pragma unroll
        for (int m = 0; m < MN; m++) {
            c1[m] = ALPHA * s[m] * inv_u / r[m];
            c2[m] = c2com * r[m];
            t[m]  = c1[m] + c2[m];
        }

        float col[MN];
        #pragma unroll
        for (int n = 0; n < MN; n++) col[n] = 0.f;
        float norminf = 0.f;

        #pragma unroll
        for (int m = 0; m < MN; m++) {
            float Mrow[CN];
            #pragma unroll
            for (int j = 0; j < CN; j++)
                Mrow[j] = c1[m] * wg[m * CN + j] + c2[m] * wg[MN * CN + j] - t[m] * q[j];
            float wm = c1[m] * q[m] + c2[m] * q[MN] - t[m] * qs;
            float rowsum = 0.f;
            #pragma unroll
            for (int n = 0; n < MN; n++) {
                float g2 = c1[n] * Mrow[n] + c2[n] * Mrow[MN] - t[n] * wm;
                float ag = fabsf(g2);
                rowsum += ag;
                col[n] += ag;
            }
            norminf = fmaxf(norminf, rowsum);
        }
        float norm1 = 0.f;
        #pragma unroll
        for (int n = 0; n < MN; n++) norm1 = fmaxf(norm1, col[n]);

        float u2 = u * u;
        float jn = u2 * sqrtf(norm1 * norminf);
        out[s0 + tid] = delta / (0.1f * jn);
    }
}

// ---------------------------------------------------------------------------
extern "C" void kernel_launch(void* const* d_in, const int* in_sizes, int n_in,
                              void* d_out, int out_size) {
    const float* data = (const float*)d_in[0];   // [2048,3,32,32]
    const float* W    = (const float*)d_in[1];   // [3072,10]
    const float* bias = (const float*)d_in[2];   // [10]
    float* out = (float*)d_out;                  // [2048,1]

    static int configured = 0;
    if (!configured) {
        cudaFuncSetAttribute(main_kernel,
                             cudaFuncAttributeMaxDynamicSharedMemorySize,
                             90112);
        configured = 1;
    }

    prep_kernel<<<22, 256>>>(W);
    main_kernel<<<148, 512, 86016>>>(data, bias, out);
}